// round 16
// baseline (speedup 1.0000x reference)
#include <cuda_runtime.h>
#include <cuda_bf16.h>
#include <math.h>
#include <stdint.h>

#define Vv     50257
#define Sdim   2048
#define Hdim   1024
#define H2     2048
#define IN3    3072
#define G4     4096
#define PROBN  (Vv + Sdim)   /* 52305 */
#define P1B    50            /* phase-1 blocks over score_g [0,50257) */
#define FINB   148           /* fused-final blocks (== SM count) */

/* ------------------------- device scratch (no allocs) ------------------- */
__device__ float g_logits[Sdim];
__device__ float g_rho[Sdim];
__device__ float g_colpart[64][2][H2];
__device__ float g_ctx[H2];
__device__ float g_rhoenc[H2];
__device__ float g_lstm_in[IN3];
__device__ float g_gates[G4];
__device__ float g_h1[Hdim];
__device__ float g_c1[Hdim];
__device__ float g_tanh[(size_t)Sdim * Hdim];   /* tanh(enc@Wc.T+b) matrix */
__device__ float g_smax[P1B], g_ssum[P1B];
__device__ float g_smax2[FINB], g_ssum2[FINB];
__device__ int   g_ctr;
__device__ volatile int g_done;
__device__ float g_M, g_Z;

/* ------------------------- math helpers (fast-math safe) ---------------- */
__device__ __forceinline__ float sigmoid_acc(float x) {
    return 1.0f / (1.0f + expf(-x));
}
__device__ __forceinline__ float tanh_acc(float x) {
    return 1.0f - 2.0f / (expf(2.0f * x) + 1.0f);
}
__device__ __forceinline__ float dot4(float4 a, float4 b) {
    return a.x * b.x + a.y * b.y + a.z * b.z + a.w * b.w;
}
__device__ __forceinline__ float warp_red(float v) {
#pragma unroll
    for (int s = 16; s > 0; s >>= 1) v += __shfl_down_sync(0xffffffffu, v, s);
    return v;
}

__device__ __forceinline__ uint32_t smem_u32(const void* p) {
    uint32_t a;
    asm("{ .reg .u64 t; cvta.to.shared.u64 t, %1; cvt.u32.u64 %0, t; }" : "=r"(a) : "l"(p));
    return a;
}

__device__ __forceinline__ void mma16816(float* c, const uint32_t* a, const uint32_t* b) {
    asm volatile(
        "mma.sync.aligned.m16n8k16.row.col.f32.bf16.bf16.f32 "
        "{%0,%1,%2,%3}, {%4,%5,%6,%7}, {%8,%9}, {%0,%1,%2,%3};"
        : "+f"(c[0]), "+f"(c[1]), "+f"(c[2]), "+f"(c[3])
        : "r"(a[0]), "r"(a[1]), "r"(a[2]), "r"(a[3]), "r"(b[0]), "r"(b[1]));
}
__device__ __forceinline__ void ldmx4(uint32_t* r, uint32_t addr) {
    asm volatile("ldmatrix.sync.aligned.m8n8.x4.shared.b16 {%0,%1,%2,%3}, [%4];"
        : "=r"(r[0]), "=r"(r[1]), "=r"(r[2]), "=r"(r[3]) : "r"(addr));
}
/* split two fp32 into packed bf16 hi + bf16 lo words */
__device__ __forceinline__ void split2(float a, float b, uint32_t& hi, uint32_t& lo) {
    asm("cvt.rn.bf16x2.f32 %0, %1, %2;" : "=r"(hi) : "f"(b), "f"(a));
    float ha = __uint_as_float(hi << 16);
    float hb = __uint_as_float(hi & 0xffff0000u);
    asm("cvt.rn.bf16x2.f32 %0, %1, %2;" : "=r"(lo) : "f"(b - hb), "f"(a - ha));
}

/* --------- K0: reset fused-final counter/flag (ordered first) ------------ */
__global__ void k_reset() { g_ctr = 0; g_done = 0; }

/* ------------- K1: attention logits GEMV (warp per row, 8 rows/blk) ------ */
__global__ void k_attn(const float* __restrict__ x, const float* __restrict__ h0,
                       const float* __restrict__ W, const float* __restrict__ b) {
    __shared__ float4 vec[512];
    int t = threadIdx.x;
    if (t < 256) { vec[t] = ((const float4*)x)[t]; vec[t + 256] = ((const float4*)h0)[t]; }
    __syncthreads();
    int warp = t >> 5, lane = t & 31;
    int row = blockIdx.x * 8 + warp;
    const float4* Wr = (const float4*)(W + (size_t)row * H2);
    float acc = 0.f;
#pragma unroll
    for (int i = 0; i < 16; i++) {
        int f = lane + i * 32;
        acc += dot4(Wr[f], vec[f]);
    }
    acc = warp_red(acc);
    if (lane == 0) g_logits[row] = acc + b[row];
}

/* --------------- K2: rho mask+normalize fused with attn softmax ---------- */
__global__ void k_rho_softmax(const int* __restrict__ sent, const float* __restrict__ prev_probs,
                              const int* __restrict__ pw) {
    int t = threadIdx.x;
    __shared__ float red[256];
    {
        int w = pw[0];
        float vals[8];
        float part = 0.f;
#pragma unroll
        for (int i = 0; i < 8; i++) {
            int s = t + i * 256;
            float v = (sent[s] == w) ? prev_probs[Vv + s] : 0.f;
            vals[i] = v; part += v;
        }
        red[t] = part; __syncthreads();
        for (int s = 128; s > 0; s >>= 1) { if (t < s) red[t] += red[t + s]; __syncthreads(); }
        float inv = 1.0f / (red[0] + 1e-9f);
#pragma unroll
        for (int i = 0; i < 8; i++) g_rho[t + i * 256] = vals[i] * inv;
        __syncthreads();
    }
    {
        float vals[8];
        float m = -1e30f;
#pragma unroll
        for (int i = 0; i < 8; i++) { vals[i] = g_logits[t + i * 256]; m = fmaxf(m, vals[i]); }
        red[t] = m; __syncthreads();
        for (int s = 128; s > 0; s >>= 1) { if (t < s) red[t] = fmaxf(red[t], red[t + s]); __syncthreads(); }
        m = red[0]; __syncthreads();
        float sum = 0.f;
#pragma unroll
        for (int i = 0; i < 8; i++) { vals[i] = __expf(vals[i] - m); sum += vals[i]; }
        red[t] = sum; __syncthreads();
        for (int s = 128; s > 0; s >>= 1) { if (t < s) red[t] += red[t + s]; __syncthreads(); }
        float inv = 1.0f / red[0];
#pragma unroll
        for (int i = 0; i < 8; i++) g_logits[t + i * 256] = vals[i] * inv;
    }
}

/* --------- K4: fused column reductions ctx & rho@enc over encoder -------- */
__global__ void k_colred(const float* __restrict__ enc) {
    int t   = threadIdx.x;
    int col = blockIdx.x * 256 + t;
    int rc  = blockIdx.y;               // 64 row chunks of 32
    __shared__ float aw[32], rw[32];
    if (t < 32) aw[t] = g_logits[rc * 32 + t];
    else if (t < 64) rw[t - 32] = g_rho[rc * 32 + (t - 32)];
    __syncthreads();
    float a = 0.f, r = 0.f;
    const float* base = enc + (size_t)(rc * 32) * H2 + col;
#pragma unroll
    for (int i = 0; i < 32; i++) {
        float v = base[(size_t)i * H2];
        a += aw[i] * v;
        r += rw[i] * v;
    }
    g_colpart[rc][0][col] = a;
    g_colpart[rc][1][col] = r;
}

__global__ void k_colfin() {
    int col = blockIdx.x * 256 + threadIdx.x;
    float a = 0.f, r = 0.f;
#pragma unroll
    for (int c = 0; c < 64; c++) { a += g_colpart[c][0][col]; r += g_colpart[c][1][col]; }
    g_ctx[col] = a;
    g_rhoenc[col] = r;
}

/* -------- K5: attentive & selective GEMVs (warp per row, 8/blk) ---------- */
__global__ void k_combws(const float* __restrict__ combW, const float* __restrict__ combb,
                         const float* __restrict__ WsW,  const float* __restrict__ Wsb) {
    __shared__ float4 vec[512];
    int t = threadIdx.x;
    bool isComb = blockIdx.x < 128;
    const float4* v4 = isComb ? (const float4*)g_ctx : (const float4*)g_rhoenc;
    if (t < 256) { vec[t] = v4[t]; vec[t + 256] = v4[t + 256]; }
    __syncthreads();
    int warp = t >> 5, lane = t & 31;
    int row = blockIdx.x * 8 + warp;     /* 0..2047 */
    int lrow = isComb ? row : row - Hdim;
    const float4* Wr = isComb ? (const float4*)(combW + (size_t)lrow * H2)
                              : (const float4*)(WsW + (size_t)lrow * H2);
    float acc = 0.f;
#pragma unroll
    for (int i = 0; i < 16; i++) {
        int f = lane + i * 32;
        acc += dot4(Wr[f], vec[f]);
    }
    acc = warp_red(acc);
    if (lane == 0) {
        if (isComb) g_lstm_in[2 * Hdim + lrow] = acc + combb[lrow];
        else        g_lstm_in[Hdim + lrow] = acc + Wsb[lrow];
    }
}

/* --------- K6a: gate GEMV pre-part (x + h0 terms; warp per row) ---------- */
__global__ void k_gates_pre(const float* __restrict__ x, const float* __restrict__ h0,
                            const float* __restrict__ Wih, const float* __restrict__ Whh,
                            const float* __restrict__ bih, const float* __restrict__ bhh) {
    __shared__ float4 vx[256], vh[256];
    int t = threadIdx.x;
    if (t < 256) { vx[t] = ((const float4*)x)[t]; vh[t] = ((const float4*)h0)[t]; }
    __syncthreads();
    int warp = t >> 5, lane = t & 31;
    int row = blockIdx.x * 8 + warp;     /* 0..4095 */
    const float4* Wi = (const float4*)(Wih + (size_t)row * IN3);
    const float4* Wh = (const float4*)(Whh + (size_t)row * Hdim);
    float acc = 0.f;
#pragma unroll
    for (int i = 0; i < 8; i++) {
        int f = lane + i * 32;
        acc += dot4(Wi[f], vx[f]);
        acc += dot4(Wh[f], vh[f]);
    }
    acc = warp_red(acc);
    if (lane == 0) g_gates[row] = acc + bih[row] + bhh[row];
}

/* --------- K6b: gate GEMV post-part (selective+attentive; warp/row) ------ */
__global__ void k_gates_post(const float* __restrict__ Wih) {
    __shared__ float4 vec[512];
    int t = threadIdx.x;
    const float4* li = (const float4*)(g_lstm_in + Hdim);
    if (t < 256) { vec[t] = li[t]; vec[t + 256] = li[t + 256]; }
    __syncthreads();
    int warp = t >> 5, lane = t & 31;
    int row = blockIdx.x * 8 + warp;
    const float4* Wi = (const float4*)(Wih + (size_t)row * IN3 + Hdim);
    float acc = 0.f;
#pragma unroll
    for (int i = 0; i < 16; i++) {
        int f = lane + i * 32;
        acc += dot4(Wi[f], vec[f]);
    }
    acc = warp_red(acc);
    if (lane == 0) g_gates[row] += acc;
}

/* --------- K7: LSTM elementwise ------------------------------------------ */
__global__ void k_lstm(const float* __restrict__ c0, float* __restrict__ out) {
    int i = blockIdx.x * 256 + threadIdx.x;
    float gi = g_gates[i];
    float gf = g_gates[Hdim + i];
    float gg = g_gates[2 * Hdim + i];
    float go = g_gates[3 * Hdim + i];
    float c1 = sigmoid_acc(gf) * c0[i] + sigmoid_acc(gi) * tanh_acc(gg);
    float h1 = sigmoid_acc(go) * tanh_acc(c1);
    g_c1[i] = c1; g_h1[i] = h1;
    out[PROBN + i] = h1;
    out[PROBN + Hdim + i] = c1;
}

/* --------- K8: vocab GEMV score_g = h1 @ Wo.T + b (warp per row) ---------- */
__global__ void k_wo(const float* __restrict__ Wo, const float* __restrict__ Wob,
                     float* __restrict__ out) {
    __shared__ float h1s[Hdim];
    int t = threadIdx.x;
    for (int i = t; i < Hdim; i += 256) h1s[i] = g_h1[i];
    __syncthreads();
    int warp = t >> 5, lane = t & 31;
    int row = blockIdx.x * 8 + warp;
    if (row >= Vv) return;
    const float4* Wr = (const float4*)(Wo + (size_t)row * Hdim);
    const float4* hv = (const float4*)h1s;
    float acc = 0.f;
#pragma unroll
    for (int i = 0; i < 8; i++) {
        int f = lane + i * 32;
        acc += dot4(Wr[f], hv[f]);
    }
    acc = warp_red(acc);
    if (lane == 0) out[row] = acc + Wob[row];
}

/* --------- K9: tanh(enc@Wc.T+b) via mma.sync with in-kernel fp32 split --- */
#define KC 32
#define ROWB 80                       /* 40 bf16 padded row = 80 bytes */
#define TILE_SB (128 * ROWB)          /* 10240 B per tile */
#define STAGE_SB (4 * TILE_SB)        /* 40960 B per stage (Ahi,Alo,Bhi,Blo) */
#define NBUF 3
#define NSTAGES (H2 / KC)             /* 64 */

__global__ __launch_bounds__(256, 1)
void k_scorec_mma(const float* __restrict__ enc, const float* __restrict__ Wc,
                  const float* __restrict__ Wcb) {
    extern __shared__ char dynsm[];
    __shared__ float bss[128];

    const int tid = threadIdx.x;
    const int wid = tid >> 5, lane = tid & 31;
    const int warpM = wid & 3, warpN = wid >> 2;   /* 4x2 warp grid */
    const int m_base = warpM * 32;
    const int n_base = warpN * 64;
    const int bm0 = blockIdx.x * 128;
    const int bn0 = blockIdx.y * 128;

    const uint32_t smbase = smem_u32(dynsm);

    if (tid < 128) bss[tid] = Wcb[bn0 + tid];

    /* loader mapping: thread t -> row r = t>>1, half h = t&1 (16 floats) */
    const int lr = tid >> 1;
    const int lh = tid & 1;
    const float4* gA = (const float4*)(enc + (size_t)(bm0 + lr) * H2) + lh * 4;
    const float4* gB = (const float4*)(Wc  + (size_t)(bn0 + lr) * H2) + lh * 4;

    float4 ra[4], rb[4];

#define LOAD_REGS(CH) do {                                                     \
        int kf4 = (CH) * (KC / 4);                                             \
        _Pragma("unroll")                                                      \
        for (int i = 0; i < 4; i++) { ra[i] = gA[kf4 + i]; rb[i] = gB[kf4 + i]; } \
    } while (0)

#define STORE_REGS(CH) do {                                                    \
        char* stage = dynsm + ((CH) % NBUF) * STAGE_SB;                        \
        uint32_t h0, h1, h2, h3, l0, l1, l2, l3;                               \
        split2(ra[0].x, ra[0].y, h0, l0);                                      \
        split2(ra[0].z, ra[0].w, h1, l1);                                      \
        split2(ra[1].x, ra[1].y, h2, l2);                                      \
        split2(ra[1].z, ra[1].w, h3, l3);                                      \
        *(uint4*)(stage + 0 * TILE_SB + lr * ROWB + lh * 32)      = make_uint4(h0,h1,h2,h3); \
        *(uint4*)(stage + 1 * TILE_SB + lr * ROWB + lh * 32)      = make_uint4(l0,l1,l2,l3); \
        split2(ra[2].x, ra[2].y, h0, l0);                                      \
        split2(ra[2].z, ra[2].w, h1, l1);                                      \
        split2(ra[3].x, ra[3].y, h2, l2);                                      \
        split2(ra[3].z, ra[3].w, h3, l3);                                      \
        *(uint4*)(stage + 0 * TILE_SB + lr * ROWB + lh * 32 + 16) = make_uint4(h0,h1,h2,h3); \
        *(uint4*)(stage + 1 * TILE_SB + lr * ROWB + lh * 32 + 16) = make_uint4(l0,l1,l2,l3); \
        split2(rb[0].x, rb[0].y, h0, l0);                                      \
        split2(rb[0].z, rb[0].w, h1, l1);                                      \
        split2(rb[1].x, rb[1].y, h2, l2);                                      \
        split2(rb[1].z, rb[1].w, h3, l3);                                      \
        *(uint4*)(stage + 2 * TILE_SB + lr * ROWB + lh * 32)      = make_uint4(h0,h1,h2,h3); \
        *(uint4*)(stage + 3 * TILE_SB + lr * ROWB + lh * 32)      = make_uint4(l0,l1,l2,l3); \
        split2(rb[2].x, rb[2].y, h0, l0);                                      \
        split2(rb[2].z, rb[2].w, h1, l1);                                      \
        split2(rb[3].x, rb[3].y, h2, l2);                                      \
        split2(rb[3].z, rb[3].w, h3, l3);                                      \
        *(uint4*)(stage + 2 * TILE_SB + lr * ROWB + lh * 32 + 16) = make_uint4(h0,h1,h2,h3); \
        *(uint4*)(stage + 3 * TILE_SB + lr * ROWB + lh * 32 + 16) = make_uint4(l0,l1,l2,l3); \
    } while (0)

    float acc[2][8][4];
#pragma unroll
    for (int mi = 0; mi < 2; mi++)
#pragma unroll
        for (int ni = 0; ni < 8; ni++)
#pragma unroll
            for (int r = 0; r < 4; r++) acc[mi][ni][r] = 0.f;

    LOAD_REGS(0); STORE_REGS(0);
    LOAD_REGS(1); STORE_REGS(1);
    __syncthreads();

    for (int ch = 0; ch < NSTAGES; ch++) {
        if (ch + 2 < NSTAGES) LOAD_REGS(ch + 2);

        const uint32_t sb = smbase + (ch % NBUF) * STAGE_SB;
        const uint32_t ah_b = sb + 0 * TILE_SB;
        const uint32_t bh_b = sb + 2 * TILE_SB;

#pragma unroll
        for (int s = 0; s < 2; s++) {           /* two k16 slices per stage */
            const int ks4 = s * 32;             /* byte offset of slice */
            uint32_t ah[2][4], al[2][4], bh[4][4], bl[4][4];
#pragma unroll
            for (int mi = 0; mi < 2; mi++) {
                uint32_t row = m_base + mi * 16 + (lane & 15);
                uint32_t addr = ah_b + row * ROWB + ks4 + ((lane >> 4) << 4);
                ldmx4(ah[mi], addr);
                ldmx4(al[mi], addr + TILE_SB);
            }
#pragma unroll
            for (int p = 0; p < 4; p++) {
                uint32_t row = n_base + p * 16 + ((lane >> 4) << 3) + (lane & 7);
                uint32_t addr = bh_b + row * ROWB + ks4 + (((lane >> 3) & 1) << 4);
                ldmx4(bh[p], addr);
                ldmx4(bl[p], addr + TILE_SB);
            }
#pragma unroll
            for (int mi = 0; mi < 2; mi++)
#pragma unroll
                for (int ni = 0; ni < 8; ni++) {
                    const uint32_t* bhf = &bh[ni >> 1][(ni & 1) * 2];
                    const uint32_t* blf = &bl[ni >> 1][(ni & 1) * 2];
                    mma16816(acc[mi][ni], ah[mi], bhf);
                    mma16816(acc[mi][ni], ah[mi], blf);
                    mma16816(acc[mi][ni], al[mi], bhf);
                }
        }
        if (ch + 2 < NSTAGES) STORE_REGS(ch + 2);
        __syncthreads();
    }

    /* epilogue: store tanh(D + b) matrix (float2 per fragment half) */
#pragma unroll
    for (int mi = 0; mi < 2; mi++)
#pragma unroll
        for (int ni = 0; ni < 8; ni++) {
            int c0 = n_base + ni * 8 + (lane & 3) * 2;
            int r0 = m_base + mi * 16 + (lane >> 2);
            float2 v0, v1;
            v0.x = tanh_acc(acc[mi][ni][0] + bss[c0]);
            v0.y = tanh_acc(acc[mi][ni][1] + bss[c0 + 1]);
            v1.x = tanh_acc(acc[mi][ni][2] + bss[c0]);
            v1.y = tanh_acc(acc[mi][ni][3] + bss[c0 + 1]);
            *(float2*)&g_tanh[(size_t)(bm0 + r0) * Hdim + bn0 + c0]     = v0;
            *(float2*)&g_tanh[(size_t)(bm0 + r0 + 8) * Hdim + bn0 + c0] = v1;
        }
}

/* --------- K10a: softmax phase 1 over score_g [0, 50257) only ------------ */
__global__ void k_softmax_p1(const float* __restrict__ out) {
    int t = threadIdx.x, b = blockIdx.x;
    int i = b * 1024 + t;
    __shared__ float red[1024];
    float v = (i < Vv) ? out[i] : -1e30f;
    red[t] = v; __syncthreads();
    for (int s = 512; s > 0; s >>= 1) { if (t < s) red[t] = fmaxf(red[t], red[t + s]); __syncthreads(); }
    float m = red[0]; __syncthreads();
    float e = (i < Vv) ? __expf(v - m) : 0.f;
    red[t] = e; __syncthreads();
    for (int s = 512; s > 0; s >>= 1) { if (t < s) red[t] += red[t + s]; __syncthreads(); }
    if (t == 0) { g_smax[b] = m; g_ssum[b] = red[0]; }
}

/* --------- K10b: fused score_c dot + global merge + normalize ------------ */
/* grid = 148 (all resident; 1 CTA/SM guaranteed) -> in-kernel grid sync.   */
__global__ void __launch_bounds__(256, 1) k_scfin(float* __restrict__ out) {
    __shared__ float4 hv[256];
    __shared__ float rv[16];
    int t = threadIdx.x;
    hv[t] = ((const float4*)g_h1)[t];
    if (t < 16) rv[t] = -1e30f;
    __syncthreads();
    int warp = t >> 5, lane = t & 31;

    /* rows: r0 = b*8+w (always < 1184 <= 2047); r1 = r0 + 1184 if < 2048 */
    int r0 = blockIdx.x * 8 + warp;
    int r1 = r0 + 1184;
    float v0, v1 = -1e30f;
    {
        const float4* Tr = (const float4*)(g_tanh + (size_t)r0 * Hdim);
        float acc = 0.f;
#pragma unroll
        for (int i = 0; i < 8; i++) { int f = lane + i * 32; acc += dot4(Tr[f], hv[f]); }
        acc = warp_red(acc);
        v0 = __shfl_sync(0xffffffffu, acc, 0);
        if (lane == 0) out[Vv + r0] = v0;
    }
    if (r1 < Sdim) {
        const float4* Tr = (const float4*)(g_tanh + (size_t)r1 * Hdim);
        float acc = 0.f;
#pragma unroll
        for (int i = 0; i < 8; i++) { int f = lane + i * 32; acc += dot4(Tr[f], hv[f]); }
        acc = warp_red(acc);
        v1 = __shfl_sync(0xffffffffu, acc, 0);
        if (lane == 0) out[Vv + r1] = v1;
    }
    if (lane == 0) { rv[warp] = v0; rv[8 + warp] = v1; }
    __syncthreads();

    if (t == 0) {
        float m = -1e30f;
#pragma unroll
        for (int i = 0; i < 16; i++) m = fmaxf(m, rv[i]);
        float s = 0.f;
#pragma unroll
        for (int i = 0; i < 16; i++) if (rv[i] > -1e29f) s += __expf(rv[i] - m);
        g_smax2[blockIdx.x] = m; g_ssum2[blockIdx.x] = s;
        __threadfence();
        int old = atomicAdd(&g_ctr, 1);
        if (old == FINB - 1) {
            /* last block: merge all partials in fixed order (deterministic) */
            float M = -1e30f;
            for (int i = 0; i < P1B; i++)  M = fmaxf(M, g_smax[i]);
            for (int i = 0; i < FINB; i++) M = fmaxf(M, g_smax2[i]);
            float Z = 0.f;
            for (int i = 0; i < P1B; i++)  Z += g_ssum[i] * __expf(g_smax[i] - M);
            for (int i = 0; i < FINB; i++) Z += g_ssum2[i] * __expf(g_smax2[i] - M);
            g_M = M; g_Z = Z;
            __threadfence();
            g_done = 1;
        }
    }
    if (t == 0) { while (g_done == 0) { } }
    __syncthreads();

    float M = __ldcg(&g_M);
    float inv = 1.0f / __ldcg(&g_Z);
    for (int j = blockIdx.x * 256 + t; j < PROBN; j += FINB * 256)
        out[j] = __expf(out[j] - M) * inv;
}

/* ------------------------- launcher --------------------------------------- */
extern "C" void kernel_launch(void* const* d_in, const int* in_sizes, int n_in,
                              void* d_out, int out_size) {
    const float* x          = (const float*)d_in[0];
    const float* enc        = (const float*)d_in[1];
    const int*   sent       = (const int*)  d_in[2];
    const float* prev_probs = (const float*)d_in[3];
    const float* h0         = (const float*)d_in[4];
    const float* c0         = (const float*)d_in[5];
    const float* attn_W     = (const float*)d_in[6];
    const float* attn_b     = (const float*)d_in[7];
    const float* comb_W     = (const float*)d_in[8];
    const float* comb_b     = (const float*)d_in[9];
    const float* Ws_W       = (const float*)d_in[10];
    const float* Ws_b       = (const float*)d_in[11];
    const float* Wo_W       = (const float*)d_in[12];
    const float* Wo_b       = (const float*)d_in[13];
    const float* Wc_W       = (const float*)d_in[14];
    const float* Wc_b       = (const float*)d_in[15];
    const float* W_ih       = (const float*)d_in[16];
    const float* W_hh       = (const float*)d_in[17];
    const float* b_ih       = (const float*)d_in[18];
    const float* b_hh       = (const float*)d_in[19];
    const int*   pw         = (const int*)  d_in[20];
    float* out = (float*)d_out;

    cudaFuncSetAttribute(k_scorec_mma, cudaFuncAttributeMaxDynamicSharedMemorySize,
                         NBUF * STAGE_SB);

    static cudaStream_t s1 = 0, s2 = 0;
    static cudaEvent_t e0 = 0, e2 = 0, eS = 0;
    static int use_streams = -1;
    if (use_streams < 0) {
        if (cudaStreamCreateWithFlags(&s1, cudaStreamNonBlocking) == cudaSuccess &&
            cudaStreamCreateWithFlags(&s2, cudaStreamNonBlocking) == cudaSuccess &&
            cudaEventCreateWithFlags(&e0, cudaEventDisableTiming) == cudaSuccess &&
            cudaEventCreateWithFlags(&e2, cudaEventDisableTiming) == cudaSuccess &&
            cudaEventCreateWithFlags(&eS, cudaEventDisableTiming) == cudaSuccess)
            use_streams = 1;
        else
            use_streams = 0;
    }

    if (use_streams) {
        /* counter/flag reset ordered BEFORE the fork */
        k_reset<<<1, 1>>>();
        cudaEventRecord(e0, 0);
        cudaStreamWaitEvent(s1, e0, 0);
        cudaStreamWaitEvent(s2, e0, 0);

        /* s1: h1-free tanh GEMM with fused fp32 split (starts at t=0) */
        k_scorec_mma<<<dim3(16, 8), 256, NBUF * STAGE_SB, s1>>>(enc, Wc_W, Wc_b);
        cudaEventRecord(eS, s1);

        /* s2: gate pre-part */
        k_gates_pre<<<512, 256, 0, s2>>>(x, h0, W_ih, W_hh, b_ih, b_hh);
        cudaEventRecord(e2, s2);

        /* main chain to h1 */
        k_attn<<<256, 256>>>(x, h0, attn_W, attn_b);
        k_rho_softmax<<<1, 256>>>(sent, prev_probs, pw);
        k_colred<<<dim3(8, 64), 256>>>(enc);
        k_colfin<<<8, 256>>>();
        k_combws<<<256, 256>>>(comb_W, comb_b, Ws_W, Ws_b);
        cudaStreamWaitEvent(0, e2, 0);
        k_gates_post<<<512, 256>>>(W_ih);
        k_lstm<<<4, 256>>>(c0, out);

        /* main: vocab GEMV + score_g partials (hidden under scorec),
           then single fused final kernel after scorec completes */
        k_wo<<<(Vv + 7) / 8, 256>>>(Wo_W, Wo_b, out);
        k_softmax_p1<<<P1B, 1024>>>(out);
        cudaStreamWaitEvent(0, eS, 0);
        k_scfin<<<FINB, 256>>>(out);
    } else {
        k_reset<<<1, 1>>>();
        k_scorec_mma<<<dim3(16, 8), 256, NBUF * STAGE_SB>>>(enc, Wc_W, Wc_b);
        k_gates_pre<<<512, 256>>>(x, h0, W_ih, W_hh, b_ih, b_hh);
        k_attn<<<256, 256>>>(x, h0, attn_W, attn_b);
        k_rho_softmax<<<1, 256>>>(sent, prev_probs, pw);
        k_colred<<<dim3(8, 64), 256>>>(enc);
        k_colfin<<<8, 256>>>();
        k_combws<<<256, 256>>>(comb_W, comb_b, Ws_W, Ws_b);
        k_gates_post<<<512, 256>>>(W_ih);
        k_lstm<<<4, 256>>>(c0, out);
        k_wo<<<(Vv + 7) / 8, 256>>>(Wo_W, Wo_b, out);
        k_softmax_p1<<<P1B, 1024>>>(out);
        k_scfin<<<FINB, 256>>>(out);
    }
}

// round 17
// speedup vs baseline: 1.0847x; 1.0847x over previous
#include <cuda_runtime.h>
#include <cuda_bf16.h>
#include <math.h>
#include <stdint.h>

#define Vv     50257
#define Sdim   2048
#define Hdim   1024
#define H2     2048
#define IN3    3072
#define G4     4096
#define PROBN  (Vv + Sdim)   /* 52305 */
#define P1B    50            /* phase-1 blocks over score_g [0,50257) */
#define SCB    256           /* scdot blocks (partials for score_c) */

/* ------------------------- device scratch (no allocs) ------------------- */
__device__ float g_logits[Sdim];
__device__ float g_rho[Sdim];
__device__ float g_colpart[64][2][H2];
__device__ float g_ctx[H2];
__device__ float g_rhoenc[H2];
__device__ float g_lstm_in[IN3];
__device__ float g_gates[G4];
__device__ float g_h1[Hdim];
__device__ float g_c1[Hdim];
__device__ float g_tanh[(size_t)Sdim * Hdim];   /* tanh(enc@Wc.T+b) matrix */
__device__ float g_smax[P1B], g_ssum[P1B];
__device__ float g_smax2[SCB], g_ssum2[SCB];

/* ------------------------- math helpers (fast-math safe) ---------------- */
__device__ __forceinline__ float sigmoid_acc(float x) {
    return 1.0f / (1.0f + expf(-x));
}
__device__ __forceinline__ float tanh_acc(float x) {
    return 1.0f - 2.0f / (expf(2.0f * x) + 1.0f);
}
__device__ __forceinline__ float dot4(float4 a, float4 b) {
    return a.x * b.x + a.y * b.y + a.z * b.z + a.w * b.w;
}
__device__ __forceinline__ float warp_red(float v) {
#pragma unroll
    for (int s = 16; s > 0; s >>= 1) v += __shfl_down_sync(0xffffffffu, v, s);
    return v;
}

__device__ __forceinline__ uint32_t smem_u32(const void* p) {
    uint32_t a;
    asm("{ .reg .u64 t; cvta.to.shared.u64 t, %1; cvt.u32.u64 %0, t; }" : "=r"(a) : "l"(p));
    return a;
}

__device__ __forceinline__ void mma16816(float* c, const uint32_t* a, const uint32_t* b) {
    asm volatile(
        "mma.sync.aligned.m16n8k16.row.col.f32.bf16.bf16.f32 "
        "{%0,%1,%2,%3}, {%4,%5,%6,%7}, {%8,%9}, {%0,%1,%2,%3};"
        : "+f"(c[0]), "+f"(c[1]), "+f"(c[2]), "+f"(c[3])
        : "r"(a[0]), "r"(a[1]), "r"(a[2]), "r"(a[3]), "r"(b[0]), "r"(b[1]));
}
__device__ __forceinline__ void ldmx4(uint32_t* r, uint32_t addr) {
    asm volatile("ldmatrix.sync.aligned.m8n8.x4.shared.b16 {%0,%1,%2,%3}, [%4];"
        : "=r"(r[0]), "=r"(r[1]), "=r"(r[2]), "=r"(r[3]) : "r"(addr));
}
/* split two fp32 into packed bf16 hi + bf16 lo words */
__device__ __forceinline__ void split2(float a, float b, uint32_t& hi, uint32_t& lo) {
    asm("cvt.rn.bf16x2.f32 %0, %1, %2;" : "=r"(hi) : "f"(b), "f"(a));
    float ha = __uint_as_float(hi << 16);
    float hb = __uint_as_float(hi & 0xffff0000u);
    asm("cvt.rn.bf16x2.f32 %0, %1, %2;" : "=r"(lo) : "f"(b - hb), "f"(a - ha));
}

/* ------------- K1: attention logits GEMV (warp per row, 8 rows/blk) ------ */
__global__ void k_attn(const float* __restrict__ x, const float* __restrict__ h0,
                       const float* __restrict__ W, const float* __restrict__ b) {
    __shared__ float4 vec[512];
    int t = threadIdx.x;
    if (t < 256) { vec[t] = ((const float4*)x)[t]; vec[t + 256] = ((const float4*)h0)[t]; }
    __syncthreads();
    int warp = t >> 5, lane = t & 31;
    int row = blockIdx.x * 8 + warp;
    const float4* Wr = (const float4*)(W + (size_t)row * H2);
    float acc = 0.f;
#pragma unroll
    for (int i = 0; i < 16; i++) {
        int f = lane + i * 32;
        acc += dot4(Wr[f], vec[f]);
    }
    acc = warp_red(acc);
    if (lane == 0) g_logits[row] = acc + b[row];
}

/* --------------- K2: rho mask+normalize fused with attn softmax ---------- */
__global__ void k_rho_softmax(const int* __restrict__ sent, const float* __restrict__ prev_probs,
                              const int* __restrict__ pw) {
    int t = threadIdx.x;
    __shared__ float red[256];
    {
        int w = pw[0];
        float vals[8];
        float part = 0.f;
#pragma unroll
        for (int i = 0; i < 8; i++) {
            int s = t + i * 256;
            float v = (sent[s] == w) ? prev_probs[Vv + s] : 0.f;
            vals[i] = v; part += v;
        }
        red[t] = part; __syncthreads();
        for (int s = 128; s > 0; s >>= 1) { if (t < s) red[t] += red[t + s]; __syncthreads(); }
        float inv = 1.0f / (red[0] + 1e-9f);
#pragma unroll
        for (int i = 0; i < 8; i++) g_rho[t + i * 256] = vals[i] * inv;
        __syncthreads();
    }
    {
        float vals[8];
        float m = -1e30f;
#pragma unroll
        for (int i = 0; i < 8; i++) { vals[i] = g_logits[t + i * 256]; m = fmaxf(m, vals[i]); }
        red[t] = m; __syncthreads();
        for (int s = 128; s > 0; s >>= 1) { if (t < s) red[t] = fmaxf(red[t], red[t + s]); __syncthreads(); }
        m = red[0]; __syncthreads();
        float sum = 0.f;
#pragma unroll
        for (int i = 0; i < 8; i++) { vals[i] = __expf(vals[i] - m); sum += vals[i]; }
        red[t] = sum; __syncthreads();
        for (int s = 128; s > 0; s >>= 1) { if (t < s) red[t] += red[t + s]; __syncthreads(); }
        float inv = 1.0f / red[0];
#pragma unroll
        for (int i = 0; i < 8; i++) g_logits[t + i * 256] = vals[i] * inv;
    }
}

/* --------- K4: fused column reductions ctx & rho@enc over encoder -------- */
__global__ void k_colred(const float* __restrict__ enc) {
    int t   = threadIdx.x;
    int col = blockIdx.x * 256 + t;
    int rc  = blockIdx.y;               // 64 row chunks of 32
    __shared__ float aw[32], rw[32];
    if (t < 32) aw[t] = g_logits[rc * 32 + t];
    else if (t < 64) rw[t - 32] = g_rho[rc * 32 + (t - 32)];
    __syncthreads();
    float a = 0.f, r = 0.f;
    const float* base = enc + (size_t)(rc * 32) * H2 + col;
#pragma unroll
    for (int i = 0; i < 32; i++) {
        float v = base[(size_t)i * H2];
        a += aw[i] * v;
        r += rw[i] * v;
    }
    g_colpart[rc][0][col] = a;
    g_colpart[rc][1][col] = r;
}

__global__ void k_colfin() {
    int col = blockIdx.x * 256 + threadIdx.x;
    float a = 0.f, r = 0.f;
#pragma unroll
    for (int c = 0; c < 64; c++) { a += g_colpart[c][0][col]; r += g_colpart[c][1][col]; }
    g_ctx[col] = a;
    g_rhoenc[col] = r;
}

/* -------- K5: attentive & selective GEMVs (warp per row, 8/blk) ---------- */
__global__ void k_combws(const float* __restrict__ combW, const float* __restrict__ combb,
                         const float* __restrict__ WsW,  const float* __restrict__ Wsb) {
    __shared__ float4 vec[512];
    int t = threadIdx.x;
    bool isComb = blockIdx.x < 128;
    const float4* v4 = isComb ? (const float4*)g_ctx : (const float4*)g_rhoenc;
    if (t < 256) { vec[t] = v4[t]; vec[t + 256] = v4[t + 256]; }
    __syncthreads();
    int warp = t >> 5, lane = t & 31;
    int row = blockIdx.x * 8 + warp;     /* 0..2047 */
    int lrow = isComb ? row : row - Hdim;
    const float4* Wr = isComb ? (const float4*)(combW + (size_t)lrow * H2)
                              : (const float4*)(WsW + (size_t)lrow * H2);
    float acc = 0.f;
#pragma unroll
    for (int i = 0; i < 16; i++) {
        int f = lane + i * 32;
        acc += dot4(Wr[f], vec[f]);
    }
    acc = warp_red(acc);
    if (lane == 0) {
        if (isComb) g_lstm_in[2 * Hdim + lrow] = acc + combb[lrow];
        else        g_lstm_in[Hdim + lrow] = acc + Wsb[lrow];
    }
}

/* --------- K6a: gate GEMV pre-part (x + h0 terms; warp per row) ---------- */
__global__ void k_gates_pre(const float* __restrict__ x, const float* __restrict__ h0,
                            const float* __restrict__ Wih, const float* __restrict__ Whh,
                            const float* __restrict__ bih, const float* __restrict__ bhh) {
    __shared__ float4 vx[256], vh[256];
    int t = threadIdx.x;
    if (t < 256) { vx[t] = ((const float4*)x)[t]; vh[t] = ((const float4*)h0)[t]; }
    __syncthreads();
    int warp = t >> 5, lane = t & 31;
    int row = blockIdx.x * 8 + warp;     /* 0..4095 */
    const float4* Wi = (const float4*)(Wih + (size_t)row * IN3);
    const float4* Wh = (const float4*)(Whh + (size_t)row * Hdim);
    float acc = 0.f;
#pragma unroll
    for (int i = 0; i < 8; i++) {
        int f = lane + i * 32;
        acc += dot4(Wi[f], vx[f]);
        acc += dot4(Wh[f], vh[f]);
    }
    acc = warp_red(acc);
    if (lane == 0) g_gates[row] = acc + bih[row] + bhh[row];
}

/* --------- K6b: gate GEMV post-part (selective+attentive; warp/row) ------ */
__global__ void k_gates_post(const float* __restrict__ Wih) {
    __shared__ float4 vec[512];
    int t = threadIdx.x;
    const float4* li = (const float4*)(g_lstm_in + Hdim);
    if (t < 256) { vec[t] = li[t]; vec[t + 256] = li[t + 256]; }
    __syncthreads();
    int warp = t >> 5, lane = t & 31;
    int row = blockIdx.x * 8 + warp;
    const float4* Wi = (const float4*)(Wih + (size_t)row * IN3 + Hdim);
    float acc = 0.f;
#pragma unroll
    for (int i = 0; i < 16; i++) {
        int f = lane + i * 32;
        acc += dot4(Wi[f], vec[f]);
    }
    acc = warp_red(acc);
    if (lane == 0) g_gates[row] += acc;
}

/* --------- K7: LSTM elementwise ------------------------------------------ */
__global__ void k_lstm(const float* __restrict__ c0, float* __restrict__ out) {
    int i = blockIdx.x * 256 + threadIdx.x;
    float gi = g_gates[i];
    float gf = g_gates[Hdim + i];
    float gg = g_gates[2 * Hdim + i];
    float go = g_gates[3 * Hdim + i];
    float c1 = sigmoid_acc(gf) * c0[i] + sigmoid_acc(gi) * tanh_acc(gg);
    float h1 = sigmoid_acc(go) * tanh_acc(c1);
    g_c1[i] = c1; g_h1[i] = h1;
    out[PROBN + i] = h1;
    out[PROBN + Hdim + i] = c1;
}

/* --------- K8: vocab GEMV score_g = h1 @ Wo.T + b (warp per row) ---------- */
__global__ void k_wo(const float* __restrict__ Wo, const float* __restrict__ Wob,
                     float* __restrict__ out) {
    __shared__ float h1s[Hdim];
    int t = threadIdx.x;
    for (int i = t; i < Hdim; i += 256) h1s[i] = g_h1[i];
    __syncthreads();
    int warp = t >> 5, lane = t & 31;
    int row = blockIdx.x * 8 + warp;
    if (row >= Vv) return;
    const float4* Wr = (const float4*)(Wo + (size_t)row * Hdim);
    const float4* hv = (const float4*)h1s;
    float acc = 0.f;
#pragma unroll
    for (int i = 0; i < 8; i++) {
        int f = lane + i * 32;
        acc += dot4(Wr[f], hv[f]);
    }
    acc = warp_red(acc);
    if (lane == 0) out[row] = acc + Wob[row];
}

/* --------- K9: tanh(enc@Wc.T+b) via mma.sync with in-kernel fp32 split --- */
#define KC 32
#define ROWB 80                       /* 40 bf16 padded row = 80 bytes */
#define TILE_SB (128 * ROWB)          /* 10240 B per tile */
#define STAGE_SB (4 * TILE_SB)        /* 40960 B per stage (Ahi,Alo,Bhi,Blo) */
#define NBUF 3
#define NSTAGES (H2 / KC)             /* 64 */

__global__ __launch_bounds__(256, 1)
void k_scorec_mma(const float* __restrict__ enc, const float* __restrict__ Wc,
                  const float* __restrict__ Wcb) {
    extern __shared__ char dynsm[];
    __shared__ float bss[128];

    const int tid = threadIdx.x;
    const int wid = tid >> 5, lane = tid & 31;
    const int warpM = wid & 3, warpN = wid >> 2;   /* 4x2 warp grid */
    const int m_base = warpM * 32;
    const int n_base = warpN * 64;
    const int bm0 = blockIdx.x * 128;
    const int bn0 = blockIdx.y * 128;

    const uint32_t smbase = smem_u32(dynsm);

    if (tid < 128) bss[tid] = Wcb[bn0 + tid];

    /* loader mapping: thread t -> row r = t>>1, half h = t&1 (16 floats) */
    const int lr = tid >> 1;
    const int lh = tid & 1;
    const float4* gA = (const float4*)(enc + (size_t)(bm0 + lr) * H2) + lh * 4;
    const float4* gB = (const float4*)(Wc  + (size_t)(bn0 + lr) * H2) + lh * 4;

    float4 ra[4], rb[4];

#define LOAD_REGS(CH) do {                                                     \
        int kf4 = (CH) * (KC / 4);                                             \
        _Pragma("unroll")                                                      \
        for (int i = 0; i < 4; i++) { ra[i] = gA[kf4 + i]; rb[i] = gB[kf4 + i]; } \
    } while (0)

#define STORE_REGS(CH) do {                                                    \
        char* stage = dynsm + ((CH) % NBUF) * STAGE_SB;                        \
        uint32_t h0, h1, h2, h3, l0, l1, l2, l3;                               \
        split2(ra[0].x, ra[0].y, h0, l0);                                      \
        split2(ra[0].z, ra[0].w, h1, l1);                                      \
        split2(ra[1].x, ra[1].y, h2, l2);                                      \
        split2(ra[1].z, ra[1].w, h3, l3);                                      \
        *(uint4*)(stage + 0 * TILE_SB + lr * ROWB + lh * 32)      = make_uint4(h0,h1,h2,h3); \
        *(uint4*)(stage + 1 * TILE_SB + lr * ROWB + lh * 32)      = make_uint4(l0,l1,l2,l3); \
        split2(ra[2].x, ra[2].y, h0, l0);                                      \
        split2(ra[2].z, ra[2].w, h1, l1);                                      \
        split2(ra[3].x, ra[3].y, h2, l2);                                      \
        split2(ra[3].z, ra[3].w, h3, l3);                                      \
        *(uint4*)(stage + 0 * TILE_SB + lr * ROWB + lh * 32 + 16) = make_uint4(h0,h1,h2,h3); \
        *(uint4*)(stage + 1 * TILE_SB + lr * ROWB + lh * 32 + 16) = make_uint4(l0,l1,l2,l3); \
        split2(rb[0].x, rb[0].y, h0, l0);                                      \
        split2(rb[0].z, rb[0].w, h1, l1);                                      \
        split2(rb[1].x, rb[1].y, h2, l2);                                      \
        split2(rb[1].z, rb[1].w, h3, l3);                                      \
        *(uint4*)(stage + 2 * TILE_SB + lr * ROWB + lh * 32)      = make_uint4(h0,h1,h2,h3); \
        *(uint4*)(stage + 3 * TILE_SB + lr * ROWB + lh * 32)      = make_uint4(l0,l1,l2,l3); \
        split2(rb[2].x, rb[2].y, h0, l0);                                      \
        split2(rb[2].z, rb[2].w, h1, l1);                                      \
        split2(rb[3].x, rb[3].y, h2, l2);                                      \
        split2(rb[3].z, rb[3].w, h3, l3);                                      \
        *(uint4*)(stage + 2 * TILE_SB + lr * ROWB + lh * 32 + 16) = make_uint4(h0,h1,h2,h3); \
        *(uint4*)(stage + 3 * TILE_SB + lr * ROWB + lh * 32 + 16) = make_uint4(l0,l1,l2,l3); \
    } while (0)

    float acc[2][8][4];
#pragma unroll
    for (int mi = 0; mi < 2; mi++)
#pragma unroll
        for (int ni = 0; ni < 8; ni++)
#pragma unroll
            for (int r = 0; r < 4; r++) acc[mi][ni][r] = 0.f;

    LOAD_REGS(0); STORE_REGS(0);
    LOAD_REGS(1); STORE_REGS(1);
    __syncthreads();

    for (int ch = 0; ch < NSTAGES; ch++) {
        if (ch + 2 < NSTAGES) LOAD_REGS(ch + 2);

        const uint32_t sb = smbase + (ch % NBUF) * STAGE_SB;
        const uint32_t ah_b = sb + 0 * TILE_SB;
        const uint32_t bh_b = sb + 2 * TILE_SB;

#pragma unroll
        for (int s = 0; s < 2; s++) {           /* two k16 slices per stage */
            const int ks4 = s * 32;             /* byte offset of slice */
            uint32_t ah[2][4], al[2][4], bh[4][4], bl[4][4];
#pragma unroll
            for (int mi = 0; mi < 2; mi++) {
                uint32_t row = m_base + mi * 16 + (lane & 15);
                uint32_t addr = ah_b + row * ROWB + ks4 + ((lane >> 4) << 4);
                ldmx4(ah[mi], addr);
                ldmx4(al[mi], addr + TILE_SB);
            }
#pragma unroll
            for (int p = 0; p < 4; p++) {
                uint32_t row = n_base + p * 16 + ((lane >> 4) << 3) + (lane & 7);
                uint32_t addr = bh_b + row * ROWB + ks4 + (((lane >> 3) & 1) << 4);
                ldmx4(bh[p], addr);
                ldmx4(bl[p], addr + TILE_SB);
            }
#pragma unroll
            for (int mi = 0; mi < 2; mi++)
#pragma unroll
                for (int ni = 0; ni < 8; ni++) {
                    const uint32_t* bhf = &bh[ni >> 1][(ni & 1) * 2];
                    const uint32_t* blf = &bl[ni >> 1][(ni & 1) * 2];
                    mma16816(acc[mi][ni], ah[mi], bhf);
                    mma16816(acc[mi][ni], ah[mi], blf);
                    mma16816(acc[mi][ni], al[mi], bhf);
                }
        }
        if (ch + 2 < NSTAGES) STORE_REGS(ch + 2);
        __syncthreads();
    }

    /* epilogue: store tanh(D + b) matrix (float2 per fragment half) */
#pragma unroll
    for (int mi = 0; mi < 2; mi++)
#pragma unroll
        for (int ni = 0; ni < 8; ni++) {
            int c0 = n_base + ni * 8 + (lane & 3) * 2;
            int r0 = m_base + mi * 16 + (lane >> 2);
            float2 v0, v1;
            v0.x = tanh_acc(acc[mi][ni][0] + bss[c0]);
            v0.y = tanh_acc(acc[mi][ni][1] + bss[c0 + 1]);
            v1.x = tanh_acc(acc[mi][ni][2] + bss[c0]);
            v1.y = tanh_acc(acc[mi][ni][3] + bss[c0 + 1]);
            *(float2*)&g_tanh[(size_t)(bm0 + r0) * Hdim + bn0 + c0]     = v0;
            *(float2*)&g_tanh[(size_t)(bm0 + r0 + 8) * Hdim + bn0 + c0] = v1;
        }
}

/* --------- K9b: score_c = g_tanh @ h1 + fused softmax partials ----------- */
__global__ void k_scdot(float* __restrict__ out) {
    __shared__ float4 hv[256];
    __shared__ float rowv[8];
    int t = threadIdx.x;
    if (t < 256) hv[t] = ((const float4*)g_h1)[t];
    __syncthreads();
    int warp = t >> 5, lane = t & 31;
    int row = blockIdx.x * 8 + warp;
    const float4* Tr = (const float4*)(g_tanh + (size_t)row * Hdim);
    float acc = 0.f;
#pragma unroll
    for (int i = 0; i < 8; i++) {
        int f = lane + i * 32;
        acc += dot4(Tr[f], hv[f]);
    }
    acc = warp_red(acc);
    if (lane == 0) { out[Vv + row] = acc; rowv[warp] = acc; }
    __syncthreads();
    if (t == 0) {
        float m = rowv[0];
#pragma unroll
        for (int i = 1; i < 8; i++) m = fmaxf(m, rowv[i]);
        float s = 0.f;
#pragma unroll
        for (int i = 0; i < 8; i++) s += __expf(rowv[i] - m);
        g_smax2[blockIdx.x] = m; g_ssum2[blockIdx.x] = s;
    }
}

/* --------- K10a: softmax phase 1 over score_g [0, 50257) only ------------ */
__global__ void k_softmax_p1(const float* __restrict__ out) {
    int t = threadIdx.x, b = blockIdx.x;
    int i = b * 1024 + t;
    __shared__ float red[1024];
    float v = (i < Vv) ? out[i] : -1e30f;
    red[t] = v; __syncthreads();
    for (int s = 512; s > 0; s >>= 1) { if (t < s) red[t] = fmaxf(red[t], red[t + s]); __syncthreads(); }
    float m = red[0]; __syncthreads();
    float e = (i < Vv) ? __expf(v - m) : 0.f;
    red[t] = e; __syncthreads();
    for (int s = 512; s > 0; s >>= 1) { if (t < s) red[t] += red[t + s]; __syncthreads(); }
    if (t == 0) { g_smax[b] = m; g_ssum[b] = red[0]; }
}

/* --------- K10b: merge all partials + normalize --------------------------- */
__global__ void k_softmax_p2(float* __restrict__ out) {
    __shared__ float red[1024];
    int t = threadIdx.x, b = blockIdx.x;
    float m = -1e30f;
    if (t < P1B)            m = g_smax[t];
    else if (t < P1B + SCB) m = g_smax2[t - P1B];
    red[t] = m; __syncthreads();
    for (int s = 512; s > 0; s >>= 1) { if (t < s) red[t] = fmaxf(red[t], red[t + s]); __syncthreads(); }
    float M = red[0]; __syncthreads();
    float z = 0.f;
    if (t < P1B)            z = g_ssum[t] * __expf(g_smax[t] - M);
    else if (t < P1B + SCB) z = g_ssum2[t - P1B] * __expf(g_smax2[t - P1B] - M);
    red[t] = z; __syncthreads();
    for (int s = 512; s > 0; s >>= 1) { if (t < s) red[t] += red[t + s]; __syncthreads(); }
    float inv = 1.0f / red[0];
    int i = b * 1024 + t;
    if (i < PROBN) out[i] = __expf(out[i] - M) * inv;
}

/* ------------------------- launcher --------------------------------------- */
extern "C" void kernel_launch(void* const* d_in, const int* in_sizes, int n_in,
                              void* d_out, int out_size) {
    const float* x          = (const float*)d_in[0];
    const float* enc        = (const float*)d_in[1];
    const int*   sent       = (const int*)  d_in[2];
    const float* prev_probs = (const float*)d_in[3];
    const float* h0         = (const float*)d_in[4];
    const float* c0         = (const float*)d_in[5];
    const float* attn_W     = (const float*)d_in[6];
    const float* attn_b     = (const float*)d_in[7];
    const float* comb_W     = (const float*)d_in[8];
    const float* comb_b     = (const float*)d_in[9];
    const float* Ws_W       = (const float*)d_in[10];
    const float* Ws_b       = (const float*)d_in[11];
    const float* Wo_W       = (const float*)d_in[12];
    const float* Wo_b       = (const float*)d_in[13];
    const float* Wc_W       = (const float*)d_in[14];
    const float* Wc_b       = (const float*)d_in[15];
    const float* W_ih       = (const float*)d_in[16];
    const float* W_hh       = (const float*)d_in[17];
    const float* b_ih       = (const float*)d_in[18];
    const float* b_hh       = (const float*)d_in[19];
    const int*   pw         = (const int*)  d_in[20];
    float* out = (float*)d_out;

    cudaFuncSetAttribute(k_scorec_mma, cudaFuncAttributeMaxDynamicSharedMemorySize,
                         NBUF * STAGE_SB);

    static cudaStream_t s1 = 0, s2 = 0;
    static cudaEvent_t e0 = 0, e2 = 0, eL = 0, eS = 0;
    static int use_streams = -1;
    if (use_streams < 0) {
        if (cudaStreamCreateWithFlags(&s1, cudaStreamNonBlocking) == cudaSuccess &&
            cudaStreamCreateWithFlags(&s2, cudaStreamNonBlocking) == cudaSuccess &&
            cudaEventCreateWithFlags(&e0, cudaEventDisableTiming) == cudaSuccess &&
            cudaEventCreateWithFlags(&e2, cudaEventDisableTiming) == cudaSuccess &&
            cudaEventCreateWithFlags(&eL, cudaEventDisableTiming) == cudaSuccess &&
            cudaEventCreateWithFlags(&eS, cudaEventDisableTiming) == cudaSuccess)
            use_streams = 1;
        else
            use_streams = 0;
    }

    if (use_streams) {
        /* fork */
        cudaEventRecord(e0, 0);
        cudaStreamWaitEvent(s1, e0, 0);
        cudaStreamWaitEvent(s2, e0, 0);

        /* s1: h1-free tanh GEMM with fused fp32 split (starts at t=0) */
        k_scorec_mma<<<dim3(16, 8), 256, NBUF * STAGE_SB, s1>>>(enc, Wc_W, Wc_b);

        /* s2: gate pre-part */
        k_gates_pre<<<512, 256, 0, s2>>>(x, h0, W_ih, W_hh, b_ih, b_hh);
        cudaEventRecord(e2, s2);

        /* main chain to h1 */
        k_attn<<<256, 256>>>(x, h0, attn_W, attn_b);
        k_rho_softmax<<<1, 256>>>(sent, prev_probs, pw);
        k_colred<<<dim3(8, 64), 256>>>(enc);
        k_colfin<<<8, 256>>>();
        k_combws<<<256, 256>>>(comb_W, comb_b, Ws_W, Ws_b);
        cudaStreamWaitEvent(0, e2, 0);
        k_gates_post<<<512, 256>>>(W_ih);
        k_lstm<<<4, 256>>>(c0, out);
        cudaEventRecord(eL, 0);

        /* s1: score_c dot + partials (needs h1 + tanh matrix) */
        cudaStreamWaitEvent(s1, eL, 0);
        k_scdot<<<SCB, 256, 0, s1>>>(out);
        cudaEventRecord(eS, s1);

        /* main: vocab GEMV, then score_g softmax partials (hidden under
           scorec tail), then join + merge/normalize */
        k_wo<<<(Vv + 7) / 8, 256>>>(Wo_W, Wo_b, out);
        k_softmax_p1<<<P1B, 1024>>>(out);
        cudaStreamWaitEvent(0, eS, 0);
        k_softmax_p2<<<52, 1024>>>(out);
    } else {
        k_scorec_mma<<<dim3(16, 8), 256, NBUF * STAGE_SB>>>(enc, Wc_W, Wc_b);
        k_gates_pre<<<512, 256>>>(x, h0, W_ih, W_hh, b_ih, b_hh);
        k_attn<<<256, 256>>>(x, h0, attn_W, attn_b);
        k_rho_softmax<<<1, 256>>>(sent, prev_probs, pw);
        k_colred<<<dim3(8, 64), 256>>>(enc);
        k_colfin<<<8, 256>>>();
        k_combws<<<256, 256>>>(comb_W, comb_b, Ws_W, Ws_b);
        k_gates_post<<<512, 256>>>(W_ih);
        k_lstm<<<4, 256>>>(c0, out);
        k_scdot<<<SCB, 256>>>(out);
        k_wo<<<(Vv + 7) / 8, 256>>>(Wo_W, Wo_b, out);
        k_softmax_p1<<<P1B, 1024>>>(out);
        k_softmax_p2<<<52, 1024>>>(out);
    }
}